// round 3
// baseline (speedup 1.0000x reference)
#include <cuda_runtime.h>

#define BATCH 8
#define SEQ   1024
#define DIM   1024
#define HEADS 16
#define DH    64
#define INNER 1024
#define QKV_STRIDE (3 * INNER)
#define PAD 68  // smem row stride (floats), keeps 16B alignment, 68%32=4

// Scratch (static device allocations are the sanctioned workaround)
__device__ float g_qkv[(size_t)BATCH * SEQ * 3 * INNER];   // ~100 MB
__device__ float g_att[(size_t)BATCH * SEQ * INNER];       // ~33 MB

// ---------------------------------------------------------------------------
// Classic 128x128x8 fp32 SGEMM, 256 threads, 8x8 per-thread microtile.
// A: [M,K] row-major, B: [K,N] row-major, C = A*B (+bias broadcast over rows).
// All dims divide tiles exactly for this problem (no bounds checks).
// ---------------------------------------------------------------------------
__global__ __launch_bounds__(256) void sgemm_kernel(
    const float* __restrict__ A, const float* __restrict__ B,
    const float* __restrict__ bias, float* __restrict__ C,
    int M, int N, int K)
{
    __shared__ float As[8][128];   // transposed: As[k][m]
    __shared__ float Bs[8][128];   // Bs[k][n]

    const int tid  = threadIdx.x;
    const int row0 = blockIdx.y * 128;
    const int col0 = blockIdx.x * 128;

    const int ra = tid >> 1;          // 0..127  (A tile row)
    const int ca = (tid & 1) * 4;     // 0 or 4  (A tile col)
    const int rb = tid >> 5;          // 0..7    (B tile row)
    const int cb = (tid & 31) * 4;    // 0..124  (B tile col)

    const int tx = tid & 15, ty = tid >> 4;
    const int m0 = ty * 8, n0 = tx * 8;

    float acc[8][8] = {};

    const float* Aptr = A + (size_t)(row0 + ra) * K + ca;
    const float* Bptr = B + (size_t)rb * N + col0 + cb;

    for (int kt = 0; kt < K; kt += 8) {
        float4 av = *(const float4*)(Aptr + kt);
        float4 bv = *(const float4*)(Bptr + (size_t)kt * N);
        As[ca + 0][ra] = av.x;
        As[ca + 1][ra] = av.y;
        As[ca + 2][ra] = av.z;
        As[ca + 3][ra] = av.w;
        *(float4*)&Bs[rb][cb] = bv;
        __syncthreads();

        #pragma unroll
        for (int k = 0; k < 8; k++) {
            float a[8], b[8];
            *(float4*)(a)     = *(const float4*)&As[k][m0];
            *(float4*)(a + 4) = *(const float4*)&As[k][m0 + 4];
            *(float4*)(b)     = *(const float4*)&Bs[k][n0];
            *(float4*)(b + 4) = *(const float4*)&Bs[k][n0 + 4];
            #pragma unroll
            for (int i = 0; i < 8; i++)
                #pragma unroll
                for (int j = 0; j < 8; j++)
                    acc[i][j] += a[i] * b[j];
        }
        __syncthreads();
    }

    // Epilogue
    float bb[8];
    if (bias) {
        *(float4*)(bb)     = *(const float4*)&bias[col0 + n0];
        *(float4*)(bb + 4) = *(const float4*)&bias[col0 + n0 + 4];
    } else {
        #pragma unroll
        for (int j = 0; j < 8; j++) bb[j] = 0.f;
    }
    #pragma unroll
    for (int i = 0; i < 8; i++) {
        float* crow = C + (size_t)(row0 + m0 + i) * N + col0 + n0;
        float4 v0 = make_float4(acc[i][0] + bb[0], acc[i][1] + bb[1],
                                acc[i][2] + bb[2], acc[i][3] + bb[3]);
        float4 v1 = make_float4(acc[i][4] + bb[4], acc[i][5] + bb[5],
                                acc[i][6] + bb[6], acc[i][7] + bb[7]);
        *(float4*)(crow)     = v0;
        *(float4*)(crow + 4) = v1;
    }
}

// ---------------------------------------------------------------------------
// Flash attention: one CTA = 64 query rows of one (batch, head).
// Online softmax over 16 KV tiles of 64. 256 threads, 4x4 microtiles.
// Dynamic smem ~88 KB.
// ---------------------------------------------------------------------------
__global__ __launch_bounds__(256) void attn_kernel(
    const float* __restrict__ qkv, float* __restrict__ out)
{
    extern __shared__ float sm[];
    float* Qs   = sm;                 // [64][PAD] indexed [d][i] (transposed)
    float* Ks   = Qs + 64 * PAD;      // [d][j] (transposed)
    float* Vs   = Ks + 64 * PAD;      // [j][d]
    float* Ss   = Vs + 64 * PAD;      // [i][j] raw scores
    float* Pt   = Ss + 64 * PAD;      // [j][i] exp'd probs (transposed)
    float* m_sm = Pt + 64 * PAD;      // [64] running max
    float* l_sm = m_sm + 64;          // [64] running sum
    float* a_sm = l_sm + 64;          // [64] rescale factor

    const int tid = threadIdx.x;
    const int qt = blockIdx.x, h = blockIdx.y, b = blockIdx.z;

    const float* qbase = qkv + ((size_t)b * SEQ + (size_t)qt * 64) * QKV_STRIDE + h * DH;
    const float* kbase = qkv + (size_t)b * SEQ * QKV_STRIDE + INNER     + h * DH;
    const float* vbase = qkv + (size_t)b * SEQ * QKV_STRIDE + 2 * INNER + h * DH;

    // Load Q (pre-scaled by 1/sqrt(Dh)=0.125), transposed into Qs[d][i]
    for (int idx = tid; idx < 64 * 64; idx += 256) {
        int i = idx >> 6, d = idx & 63;
        Qs[d * PAD + i] = qbase[(size_t)i * QKV_STRIDE + d] * 0.125f;
    }
    if (tid < 64) { m_sm[tid] = -3.0e38f; l_sm[tid] = 0.f; }

    const int tx = tid & 15, ty = tid >> 4;
    const int i0 = ty * 4, j0 = tx * 4, d0 = tx * 4;

    float o[4][4] = {};

    for (int t = 0; t < 16; t++) {
        const float* kt_ = kbase + (size_t)t * 64 * QKV_STRIDE;
        const float* vt_ = vbase + (size_t)t * 64 * QKV_STRIDE;
        for (int idx = tid; idx < 64 * 64; idx += 256) {
            int j = idx >> 6, d = idx & 63;
            Ks[d * PAD + j] = kt_[(size_t)j * QKV_STRIDE + d];
            Vs[j * PAD + d] = vt_[(size_t)j * QKV_STRIDE + d];
        }
        __syncthreads();

        // S = Q * K^T  (64x64, inner dim d)
        float s[4][4] = {};
        #pragma unroll
        for (int d = 0; d < 64; d++) {
            float qa[4], ka[4];
            *(float4*)qa = *(const float4*)&Qs[d * PAD + i0];
            *(float4*)ka = *(const float4*)&Ks[d * PAD + j0];
            #pragma unroll
            for (int ii = 0; ii < 4; ii++)
                #pragma unroll
                for (int jj = 0; jj < 4; jj++)
                    s[ii][jj] += qa[ii] * ka[jj];
        }
        #pragma unroll
        for (int ii = 0; ii < 4; ii++)
            *(float4*)&Ss[(i0 + ii) * PAD + j0] =
                make_float4(s[ii][0], s[ii][1], s[ii][2], s[ii][3]);
        __syncthreads();

        // Online softmax: one thread per query row
        if (tid < 64) {
            const int r = tid;
            float* srow = Ss + r * PAD;
            float mt = -3.0e38f;
            #pragma unroll 8
            for (int j = 0; j < 64; j++) mt = fmaxf(mt, srow[j]);
            float mold = m_sm[r];
            float mnew = fmaxf(mold, mt);
            float alpha = __expf(mold - mnew);
            float lsum = 0.f;
            #pragma unroll 8
            for (int j = 0; j < 64; j++) {
                float p = __expf(srow[j] - mnew);
                Pt[j * PAD + r] = p;
                lsum += p;
            }
            l_sm[r] = l_sm[r] * alpha + lsum;
            m_sm[r] = mnew;
            a_sm[r] = alpha;
        }
        __syncthreads();

        // Rescale running O, then O += P * V  (inner dim j)
        float al[4];
        #pragma unroll
        for (int ii = 0; ii < 4; ii++) al[ii] = a_sm[i0 + ii];
        #pragma unroll
        for (int ii = 0; ii < 4; ii++)
            #pragma unroll
            for (int dd = 0; dd < 4; dd++)
                o[ii][dd] *= al[ii];

        #pragma unroll
        for (int j = 0; j < 64; j++) {
            float pa[4], va[4];
            *(float4*)pa = *(const float4*)&Pt[j * PAD + i0];
            *(float4*)va = *(const float4*)&Vs[j * PAD + d0];
            #pragma unroll
            for (int ii = 0; ii < 4; ii++)
                #pragma unroll
                for (int dd = 0; dd < 4; dd++)
                    o[ii][dd] += pa[ii] * va[dd];
        }
        __syncthreads();   // protect smem tiles before next iteration's loads
    }

    // Normalize and write merged-heads layout [B, N, INNER]
    float* obase = out + ((size_t)b * SEQ + (size_t)qt * 64) * INNER + h * DH;
    #pragma unroll
    for (int ii = 0; ii < 4; ii++) {
        float inv = 1.f / l_sm[i0 + ii];
        float4 v = make_float4(o[ii][0] * inv, o[ii][1] * inv,
                               o[ii][2] * inv, o[ii][3] * inv);
        *(float4*)&obase[(size_t)(i0 + ii) * INNER + d0] = v;
    }
}

// ---------------------------------------------------------------------------
// Launch
// ---------------------------------------------------------------------------
extern "C" void kernel_launch(void* const* d_in, const int* in_sizes, int n_in,
                              void* d_out, int out_size)
{
    const float* x      = (const float*)d_in[0];
    const float* w_qkv  = (const float*)d_in[1];
    const float* w_out  = (const float*)d_in[2];
    const float* b_out  = (const float*)d_in[3];
    float* out = (float*)d_out;

    float* qkv; cudaGetSymbolAddress((void**)&qkv, g_qkv);
    float* att; cudaGetSymbolAddress((void**)&att, g_att);

    const int M = BATCH * SEQ;   // 8192

    // 1) QKV projection: [8192,1024] x [1024,3072]
    sgemm_kernel<<<dim3(3 * INNER / 128, M / 128), 256>>>(
        x, w_qkv, nullptr, qkv, M, 3 * INNER, DIM);

    // 2) Flash attention
    const int smem_bytes = (5 * 64 * PAD + 3 * 64) * (int)sizeof(float);  // ~88 KB
    cudaFuncSetAttribute(attn_kernel,
                         cudaFuncAttributeMaxDynamicSharedMemorySize, smem_bytes);
    attn_kernel<<<dim3(SEQ / 64, HEADS, BATCH), 256, smem_bytes>>>(qkv, att);

    // 3) Output projection: [8192,1024] x [1024,1024] + bias
    sgemm_kernel<<<dim3(DIM / 128, M / 128), 256>>>(
        att, w_out, b_out, out, M, DIM, INNER);
}

// round 5
// speedup vs baseline: 2.6065x; 2.6065x over previous
#include <cuda_runtime.h>
#include <cstdint>

#define BATCH 8
#define SEQ   1024
#define DIM   1024
#define HEADS 16
#define DH    64
#define INNER 1024
#define QKV_STRIDE (3 * INNER)
#define PAD 68   // attention smem row stride (words): frag LDS bank = 4*r4+c4 = lane -> conflict-free

// Scratch (static device arrays: the sanctioned no-alloc workaround)
__device__ float g_qkv[(size_t)BATCH * SEQ * 3 * INNER];   // ~100 MB
__device__ float g_att[(size_t)BATCH * SEQ * INNER];       // ~33 MB

// ---------------------------------------------------------------------------
// tf32 helpers
// ---------------------------------------------------------------------------
__device__ __forceinline__ uint32_t f2t(float x) {
    uint32_t r;
    asm("cvt.rna.tf32.f32 %0, %1;" : "=r"(r) : "f"(x));
    return r;
}
__device__ __forceinline__ uint4 f2t4(float4 v) {
    return make_uint4(f2t(v.x), f2t(v.y), f2t(v.z), f2t(v.w));
}

// m16n8k8 tf32 MMA, fp32 accumulate. A row-major, B col-major.
__device__ __forceinline__ void mma8(float* c, const uint32_t* a, const uint32_t* b) {
    asm volatile(
        "mma.sync.aligned.m16n8k8.row.col.f32.tf32.tf32.f32 "
        "{%0,%1,%2,%3}, {%4,%5,%6,%7}, {%8,%9}, {%0,%1,%2,%3};\n"
        : "+f"(c[0]), "+f"(c[1]), "+f"(c[2]), "+f"(c[3])
        : "r"(a[0]), "r"(a[1]), "r"(a[2]), "r"(a[3]), "r"(b[0]), "r"(b[1]));
}

// ---------------------------------------------------------------------------
// tf32 tensor-core GEMM: C = A*B (+bias). Block 128x128, BK=16, 256 thr.
// 8 warps in 2x4 grid, warp tile 64x32 = 4(m) x 4(n) m16n8k8 frags.
// M % 128 == 0, N % 128 == 0, K % 16 == 0 (true for all calls here).
// ---------------------------------------------------------------------------
#define LDA 20   // As row stride (words): frag bank = (20*r4 + c4)%32, all distinct
#define LDB 136  // Bs row stride (words): frag bank = (8*c4 + r4)%32, all distinct

__global__ __launch_bounds__(256) void gemm_tf32(
    const float* __restrict__ A, const float* __restrict__ B,
    const float* __restrict__ bias, float* __restrict__ C,
    int M, int N, int K)
{
    __shared__ uint32_t As[128 * LDA];   // [m][k] tf32 bits
    __shared__ uint32_t Bs[16 * LDB];    // [k][n] tf32 bits

    const int tid  = threadIdx.x;
    const int lane = tid & 31;
    const int warp = tid >> 5;
    const int row0 = blockIdx.y * 128;
    const int col0 = blockIdx.x * 128;

    const int wm = (warp >> 2) * 64;   // warp row block within CTA tile
    const int wn = (warp & 3) * 32;    // warp col block
    const int r4 = lane >> 2, c4 = lane & 3;

    float acc[4][4][4] = {};

    for (int kt = 0; kt < K; kt += 16) {
        // Cooperative loads (convert fp32 -> tf32 bits on store)
        #pragma unroll
        for (int it = 0; it < 2; it++) {
            int idx = tid + it * 256;            // 0..511 float4s
            int m  = idx >> 2,  k0 = (idx & 3) * 4;
            float4 av = *(const float4*)(A + (size_t)(row0 + m) * K + kt + k0);
            *(uint4*)&As[m * LDA + k0] = f2t4(av);
            int kb = idx >> 5,  n0 = (idx & 31) * 4;
            float4 bv = *(const float4*)(B + (size_t)(kt + kb) * N + col0 + n0);
            *(uint4*)&Bs[kb * LDB + n0] = f2t4(bv);
        }
        __syncthreads();

        #pragma unroll
        for (int kk = 0; kk < 2; kk++) {
            const int kc = kk * 8 + c4;
            uint32_t a[4][4], b[4][2];
            #pragma unroll
            for (int fm = 0; fm < 4; fm++) {
                int r = wm + fm * 16 + r4;
                a[fm][0] = As[r * LDA + kc];
                a[fm][1] = As[(r + 8) * LDA + kc];
                a[fm][2] = As[r * LDA + kc + 4];
                a[fm][3] = As[(r + 8) * LDA + kc + 4];
            }
            #pragma unroll
            for (int fn = 0; fn < 4; fn++) {
                int n = wn + fn * 8 + r4;
                b[fn][0] = Bs[kc * LDB + n];
                b[fn][1] = Bs[(kc + 4) * LDB + n];
            }
            #pragma unroll
            for (int fm = 0; fm < 4; fm++)
                #pragma unroll
                for (int fn = 0; fn < 4; fn++)
                    mma8(acc[fm][fn], a[fm], b[fn]);
        }
        __syncthreads();
    }

    // Epilogue: c-frag mapping rows r4/r4+8, cols 2*c4, 2*c4+1
    #pragma unroll
    for (int fm = 0; fm < 4; fm++) {
        #pragma unroll
        for (int fn = 0; fn < 4; fn++) {
            int row = row0 + wm + fm * 16 + r4;
            int col = col0 + wn + fn * 8 + c4 * 2;
            float b0 = 0.f, b1 = 0.f;
            if (bias) { b0 = bias[col]; b1 = bias[col + 1]; }
            float2 v0 = make_float2(acc[fm][fn][0] + b0, acc[fm][fn][1] + b1);
            float2 v1 = make_float2(acc[fm][fn][2] + b0, acc[fm][fn][3] + b1);
            *(float2*)&C[(size_t)row * N + col]       = v0;
            *(float2*)&C[(size_t)(row + 8) * N + col] = v1;
        }
    }
}

// ---------------------------------------------------------------------------
// Flash attention with tf32 MMAs. CTA = 64 query rows of one (b,h).
// 8 warps: warp w handles rows (w/2)*16, cols (w%2)*32 of the 64x64 S/O tile.
// Online softmax (4 threads/row). O kept in MMA accumulator fragments.
// ---------------------------------------------------------------------------
__global__ __launch_bounds__(256) void attn_tf32(
    const float* __restrict__ qkv, float* __restrict__ out)
{
    extern __shared__ uint32_t smu[];
    uint32_t* Qs = smu;                         // [i][d] tf32 (pre-scaled)
    uint32_t* Ks = Qs + 64 * PAD;               // [j][d] tf32  (== col-major B for S)
    uint32_t* Vt = Ks + 64 * PAD;               // [d][j] tf32  (== col-major B for PV)
    float*    Ss = (float*)(Vt + 64 * PAD);     // [i][j] scores
    uint32_t* Ps = (uint32_t*)(Ss + 64 * PAD);  // [i][j] probs tf32
    float* m_sm = (float*)(Ps + 64 * PAD);
    float* l_sm = m_sm + 64;
    float* a_sm = l_sm + 64;

    const int tid  = threadIdx.x;
    const int lane = tid & 31;
    const int warp = tid >> 5;
    const int qt = blockIdx.x, h = blockIdx.y, b = blockIdx.z;

    const int wm = (warp >> 1) * 16;  // 0,16,32,48
    const int wn = (warp & 1) * 32;   // 0,32
    const int r4 = lane >> 2, c4 = lane & 3;

    const float* qbase = qkv + ((size_t)b * SEQ + (size_t)qt * 64) * QKV_STRIDE + h * DH;
    const float* kbase = qkv + (size_t)b * SEQ * QKV_STRIDE + INNER     + h * DH;
    const float* vbase = qkv + (size_t)b * SEQ * QKV_STRIDE + 2 * INNER + h * DH;

    // Load Q, pre-scaled by 1/sqrt(Dh)=0.125, converted to tf32
    #pragma unroll
    for (int it = 0; it < 4; it++) {
        int idx = (tid + it * 256) * 4;         // element index, 64*64 total
        int i = idx >> 6, d = idx & 63;
        float4 v = *(const float4*)(qbase + (size_t)i * QKV_STRIDE + d);
        v.x *= 0.125f; v.y *= 0.125f; v.z *= 0.125f; v.w *= 0.125f;
        *(uint4*)&Qs[i * PAD + d] = f2t4(v);
    }
    if (tid < 64) { m_sm[tid] = -3.0e38f; l_sm[tid] = 0.f; }

    float o[4][4] = {};   // O accumulator frags: [fn][4]

    for (int t = 0; t < 16; t++) {
        const float* kt_ = kbase + (size_t)t * 64 * QKV_STRIDE;
        const float* vt_ = vbase + (size_t)t * 64 * QKV_STRIDE;
        #pragma unroll
        for (int it = 0; it < 4; it++) {
            int idx = (tid + it * 256) * 4;
            int j = idx >> 6, d = idx & 63;
            float4 kv = *(const float4*)(kt_ + (size_t)j * QKV_STRIDE + d);
            *(uint4*)&Ks[j * PAD + d] = f2t4(kv);
            float4 vv = *(const float4*)(vt_ + (size_t)j * QKV_STRIDE + d);
            Vt[(d + 0) * PAD + j] = f2t(vv.x);
            Vt[(d + 1) * PAD + j] = f2t(vv.y);
            Vt[(d + 2) * PAD + j] = f2t(vv.z);
            Vt[(d + 3) * PAD + j] = f2t(vv.w);
        }
        __syncthreads();

        // ---- S = Q * K^T (64x64, inner d=64) ----
        float s[4][4] = {};
        #pragma unroll
        for (int kk = 0; kk < 8; kk++) {
            const int kc = kk * 8 + c4;
            uint32_t a[4];
            a[0] = Qs[(wm + r4) * PAD + kc];
            a[1] = Qs[(wm + r4 + 8) * PAD + kc];
            a[2] = Qs[(wm + r4) * PAD + kc + 4];
            a[3] = Qs[(wm + r4 + 8) * PAD + kc + 4];
            #pragma unroll
            for (int fn = 0; fn < 4; fn++) {
                int n = wn + fn * 8 + r4;
                uint32_t bf[2];
                bf[0] = Ks[n * PAD + kc];
                bf[1] = Ks[n * PAD + kc + 4];
                mma8(s[fn], a, bf);
            }
        }
        // store S to smem
        #pragma unroll
        for (int fn = 0; fn < 4; fn++) {
            int col = wn + fn * 8 + c4 * 2;
            *(float2*)&Ss[(wm + r4) * PAD + col]     = make_float2(s[fn][0], s[fn][1]);
            *(float2*)&Ss[(wm + r4 + 8) * PAD + col] = make_float2(s[fn][2], s[fn][3]);
        }
        __syncthreads();

        // ---- online softmax: 4 threads per row, 16 cols each ----
        {
            const int r = tid >> 2, part = tid & 3;
            const float* srow = Ss + r * PAD + part * 16;
            float mt = -3.0e38f;
            #pragma unroll
            for (int j = 0; j < 16; j++) mt = fmaxf(mt, srow[j]);
            mt = fmaxf(mt, __shfl_xor_sync(0xffffffffu, mt, 1));
            mt = fmaxf(mt, __shfl_xor_sync(0xffffffffu, mt, 2));
            float mold = m_sm[r];
            float mnew = fmaxf(mold, mt);
            float lsum = 0.f;
            uint32_t* prow = Ps + r * PAD + part * 16;
            #pragma unroll
            for (int j = 0; j < 16; j++) {
                float p = __expf(srow[j] - mnew);
                prow[j] = f2t(p);
                lsum += p;
            }
            lsum += __shfl_xor_sync(0xffffffffu, lsum, 1);
            lsum += __shfl_xor_sync(0xffffffffu, lsum, 2);
            if (part == 0) {
                float alpha = __expf(mold - mnew);
                l_sm[r] = l_sm[r] * alpha + lsum;
                m_sm[r] = mnew;
                a_sm[r] = alpha;
            }
        }
        __syncthreads();

        // ---- rescale running O, then O += P * V (inner j=64) ----
        {
            float al0 = a_sm[wm + r4], al1 = a_sm[wm + r4 + 8];
            #pragma unroll
            for (int fn = 0; fn < 4; fn++) {
                o[fn][0] *= al0; o[fn][1] *= al0;
                o[fn][2] *= al1; o[fn][3] *= al1;
            }
        }
        #pragma unroll
        for (int kk = 0; kk < 8; kk++) {
            const int jc = kk * 8 + c4;
            uint32_t a[4];
            a[0] = Ps[(wm + r4) * PAD + jc];
            a[1] = Ps[(wm + r4 + 8) * PAD + jc];
            a[2] = Ps[(wm + r4) * PAD + jc + 4];
            a[3] = Ps[(wm + r4 + 8) * PAD + jc + 4];
            #pragma unroll
            for (int fn = 0; fn < 4; fn++) {
                int d = wn + fn * 8 + r4;
                uint32_t bf[2];
                bf[0] = Vt[d * PAD + jc];
                bf[1] = Vt[d * PAD + jc + 4];
                mma8(o[fn], a, bf);
            }
        }
        __syncthreads();   // before next tile's K/V overwrite
    }

    // ---- normalize and write merged-heads [B, N, INNER] ----
    float inv0 = 1.f / l_sm[wm + r4];
    float inv1 = 1.f / l_sm[wm + r4 + 8];
    float* obase = out + ((size_t)b * SEQ + (size_t)qt * 64) * INNER + h * DH;
    #pragma unroll
    for (int fn = 0; fn < 4; fn++) {
        int col = wn + fn * 8 + c4 * 2;
        *(float2*)&obase[(size_t)(wm + r4) * INNER + col] =
            make_float2(o[fn][0] * inv0, o[fn][1] * inv0);
        *(float2*)&obase[(size_t)(wm + r4 + 8) * INNER + col] =
            make_float2(o[fn][2] * inv1, o[fn][3] * inv1);
    }
}

// ---------------------------------------------------------------------------
// Launch
// ---------------------------------------------------------------------------
extern "C" void kernel_launch(void* const* d_in, const int* in_sizes, int n_in,
                              void* d_out, int out_size)
{
    const float* x      = (const float*)d_in[0];
    const float* w_qkv  = (const float*)d_in[1];
    const float* w_out  = (const float*)d_in[2];
    const float* b_out  = (const float*)d_in[3];
    float* out = (float*)d_out;

    float* qkv; cudaGetSymbolAddress((void**)&qkv, g_qkv);
    float* att; cudaGetSymbolAddress((void**)&att, g_att);

    const int M = BATCH * SEQ;   // 8192

    // 1) QKV projection: [8192,1024] x [1024,3072]
    gemm_tf32<<<dim3(3 * INNER / 128, M / 128), 256>>>(
        x, w_qkv, nullptr, qkv, M, 3 * INNER, DIM);

    // 2) Flash attention (tensor-core)
    const int smem_bytes = (5 * 64 * PAD + 3 * 64) * (int)sizeof(float);  // ~88 KB
    cudaFuncSetAttribute(attn_tf32,
                         cudaFuncAttributeMaxDynamicSharedMemorySize, smem_bytes);
    attn_tf32<<<dim3(SEQ / 64, HEADS, BATCH), 256, smem_bytes>>>(qkv, att);

    // 3) Output projection: [8192,1024] x [1024,1024] + bias
    gemm_tf32<<<dim3(DIM / 128, M / 128), 256>>>(
        att, w_out, b_out, out, M, DIM, INNER);
}